// round 2
// baseline (speedup 1.0000x reference)
#include <cuda_runtime.h>
#include <cuda_fp16.h>
#include <cstdint>

#define BB 64
#define TT 256
#define II 1024
#define HH 2048
#define OO 1024

// ---------------- device scratch ----------------
__device__ __half g_xh[(size_t)BB * TT * II];
__device__ __half g_Wax[(size_t)HH * II];
__device__ __half g_Waa[(size_t)HH * HH];
__device__ __half g_Wya[(size_t)OO * HH];
__device__ float  g_Z[(size_t)TT * BB * HH];      // x W_ax^T + b_ax + b_aa (fp32)
__device__ __half g_a[2][(size_t)BB * HH];        // double-buffered hidden state
__device__ unsigned g_bar;

// ---------------- helpers ----------------
__device__ __forceinline__ uint32_t sptr(const void* p) {
    return (uint32_t)__cvta_generic_to_shared(p);
}
__device__ __forceinline__ void cp_async16(const void* dst_smem, const void* src) {
    asm volatile("cp.async.cg.shared.global [%0], [%1], 16;"
                 :: "r"(sptr(dst_smem)), "l"(src));
}
__device__ __forceinline__ void cp_commit() { asm volatile("cp.async.commit_group;"); }
__device__ __forceinline__ void cp_wait0()  { asm volatile("cp.async.wait_group 0;"); }
__device__ __forceinline__ void cp_wait1()  { asm volatile("cp.async.wait_group 1;"); }

__device__ __forceinline__ void ldsm4(uint32_t& r0, uint32_t& r1, uint32_t& r2, uint32_t& r3,
                                      const void* p) {
    asm volatile("ldmatrix.sync.aligned.m8n8.x4.shared.b16 {%0,%1,%2,%3},[%4];"
                 : "=r"(r0), "=r"(r1), "=r"(r2), "=r"(r3) : "r"(sptr(p)));
}
__device__ __forceinline__ void mma16816(float* c,
                                         uint32_t a0, uint32_t a1, uint32_t a2, uint32_t a3,
                                         uint32_t b0, uint32_t b1) {
    asm volatile("mma.sync.aligned.m16n8k16.row.col.f32.f16.f16.f32 "
                 "{%0,%1,%2,%3},{%4,%5,%6,%7},{%8,%9},{%0,%1,%2,%3};"
                 : "+f"(c[0]), "+f"(c[1]), "+f"(c[2]), "+f"(c[3])
                 : "r"(a0), "r"(a1), "r"(a2), "r"(a3), "r"(b0), "r"(b1));
}
__device__ __forceinline__ float sigf(float v) { return 1.0f / (1.0f + __expf(-v)); }

// ---------------- prep ----------------
#define NX  ((size_t)BB * TT * II)
#define NAA ((size_t)HH * HH)
#define NAX ((size_t)HH * II)
#define NYA ((size_t)OO * HH)
#define NA0 ((size_t)BB * HH)
#define NPREP (NX + NAA + NAX + NYA + NA0)

__global__ void prep_kernel(const float* __restrict__ x, const float* __restrict__ Waa,
                            const float* __restrict__ Wax, const float* __restrict__ Wya) {
    size_t i = (size_t)blockIdx.x * blockDim.x + threadIdx.x;
    if (i == 0) g_bar = 0u;
    if (i < NX) { g_xh[i] = __float2half_rn(x[i]); return; }
    i -= NX;
    if (i < NAA) { g_Waa[i] = __float2half_rn(Waa[i]); return; }
    i -= NAA;
    if (i < NAX) { g_Wax[i] = __float2half_rn(Wax[i]); return; }
    i -= NAX;
    if (i < NYA) { g_Wya[i] = __float2half_rn(Wya[i]); return; }
    i -= NYA;
    if (i < NA0) { g_a[0][i] = __ushort_as_half((unsigned short)0); }
}

// ---------------- xproj: Z = x W_ax^T + biases ----------------
// CTA tile 128(M) x 128(N), K chunks of 64, double-buffered cp.async.
// 8 warps = 4(m) x 2(n); warp tile m32 x n64.
#define XP_SMEM (2 * (2 * 128 * 72 * 2))   // As + Bs, each [2][128][72] halves

__global__ void __launch_bounds__(256) xproj_kernel(const float* __restrict__ b_aa,
                                                    const float* __restrict__ b_ax) {
    extern __shared__ __align__(16) unsigned char smraw[];
    __half* As = (__half*)smraw;                       // [2][128][72]
    __half* Bs = (__half*)(smraw + 2 * 128 * 72 * 2);  // [2][128][72]

    const int tid = threadIdx.x;
    const int lane = tid & 31, warp = tid >> 5;
    const int n0 = blockIdx.x * 128;
    const int m0 = blockIdx.y * 128;
    const int wm = (warp >> 1) * 32;
    const int wn = (warp & 1) * 64;
    const int gr = lane >> 2, q = lane & 3;

    const int arow = ((lane >> 3) & 1) * 8 + (lane & 7);
    const int akoff = (lane >> 4) * 8;
    const int brow = (lane >> 4) * 8 + (lane & 7);
    const int bkoff = ((lane >> 3) & 1) * 8;

    float acc[2][8][4];
#pragma unroll
    for (int f = 0; f < 2; ++f)
#pragma unroll
        for (int bt = 0; bt < 8; ++bt)
#pragma unroll
            for (int c = 0; c < 4; ++c) acc[f][bt][c] = 0.0f;

    auto load_chunk = [&](int buf, int ck) {
#pragma unroll
        for (int r = 0; r < 4; ++r) {
            int u = tid + r * 256;          // 0..1023
            int row = u >> 3, cg = u & 7;
            int m = m0 + row;
            int t = m >> 6, b = m & 63;
            cp_async16(As + buf * (128 * 72) + row * 72 + cg * 8,
                       g_xh + ((size_t)b * TT + t) * II + ck * 64 + cg * 8);
            cp_async16(Bs + buf * (128 * 72) + row * 72 + cg * 8,
                       g_Wax + (size_t)(n0 + row) * II + ck * 64 + cg * 8);
        }
    };

    load_chunk(0, 0);
    cp_commit();
    const int NCH = II / 64;  // 16
    for (int ck = 0; ck < NCH; ++ck) {
        if (ck + 1 < NCH) { load_chunk((ck + 1) & 1, ck + 1); cp_commit(); cp_wait1(); }
        else cp_wait0();
        __syncthreads();
        const __half* Ab = As + (ck & 1) * (128 * 72);
        const __half* Bb = Bs + (ck & 1) * (128 * 72);
#pragma unroll
        for (int s = 0; s < 4; ++s) {
            uint32_t a[2][4];
#pragma unroll
            for (int f = 0; f < 2; ++f)
                ldsm4(a[f][0], a[f][1], a[f][2], a[f][3],
                      Ab + (wm + f * 16 + arow) * 72 + s * 16 + akoff);
#pragma unroll
            for (int bp = 0; bp < 4; ++bp) {
                uint32_t b0, b1, b2, b3;
                ldsm4(b0, b1, b2, b3,
                      Bb + (wn + bp * 16 + brow) * 72 + s * 16 + bkoff);
#pragma unroll
                for (int f = 0; f < 2; ++f) {
                    mma16816(acc[f][2 * bp],     a[f][0], a[f][1], a[f][2], a[f][3], b0, b1);
                    mma16816(acc[f][2 * bp + 1], a[f][0], a[f][1], a[f][2], a[f][3], b2, b3);
                }
            }
        }
        __syncthreads();
    }

    // epilogue: add biases, store fp32 Z. Z row index == global m == t*64+b.
    float bs0[8], bs1[8];
#pragma unroll
    for (int bt = 0; bt < 8; ++bt) {
        int n = n0 + wn + bt * 8 + 2 * q;
        bs0[bt] = b_ax[n] + b_aa[n];
        bs1[bt] = b_ax[n + 1] + b_aa[n + 1];
    }
#pragma unroll
    for (int f = 0; f < 2; ++f) {
#pragma unroll
        for (int bt = 0; bt < 8; ++bt) {
            int mlo = wm + f * 16 + gr;
            int n = wn + bt * 8 + 2 * q;
            size_t zi = (size_t)(m0 + mlo) * HH + n0 + n;
            *(float2*)(g_Z + zi) =
                make_float2(acc[f][bt][0] + bs0[bt], acc[f][bt][1] + bs1[bt]);
            *(float2*)(g_Z + zi + (size_t)8 * HH) =
                make_float2(acc[f][bt][2] + bs0[bt], acc[f][bt][3] + bs1[bt]);
        }
    }
}

// ---------------- persistent recurrence ----------------
// 96 CTAs: 0..63 own 32-col slices of W_aa, 64..95 own 32-col slices of W_ya.
// Weights live in SMEM for the whole sequence. One grid barrier per step.
#define NCTA 96
#define WPAD 2056
#define PERS_SMEM (32 * WPAD * 2 + 2 * 64 * 72 * 2)   // 131584 + 18432 = 150016 B

__global__ void __launch_bounds__(256) rnn_persistent(float* __restrict__ out,
                                                      const float* __restrict__ b_ya) {
    extern __shared__ __align__(16) unsigned char smraw[];
    __half* Wsm = (__half*)smraw;                       // [32][WPAD]
    __half* Asm = (__half*)(smraw + 32 * WPAD * 2);     // [2][64][72]

    const int tid = threadIdx.x;
    const int lane = tid & 31, warp = tid >> 5;
    const int cta = blockIdx.x;
    const bool is_aa = (cta < 64);
    const int n0 = is_aa ? cta * 32 : (cta - 64) * 32;
    const __half* Wg = is_aa ? g_Waa : g_Wya;

    // preload persistent 32 x 2048 weight slice
    for (int u = tid; u < 32 * 256; u += 256) {
        int row = u >> 8, cg = u & 255;
        cp_async16(Wsm + row * WPAD + cg * 8, Wg + (size_t)(n0 + row) * HH + cg * 8);
    }
    cp_commit();
    cp_wait0();
    __syncthreads();

    const int wm = (warp >> 1) * 16;   // 4 m-groups of 16 batch rows
    const int nof = (warp & 1) * 16;   // 2 n-groups of 16 cols
    const int gr = lane >> 2, q = lane & 3;
    const int arow = ((lane >> 3) & 1) * 8 + (lane & 7);
    const int akoff = (lane >> 4) * 8;
    const int brow = (lane >> 4) * 8 + (lane & 7);
    const int bkoff = ((lane >> 3) & 1) * 8;

    // per-thread output bias (ya CTAs)
    float by[2][2];
    if (!is_aa) {
#pragma unroll
        for (int j = 0; j < 2; ++j) {
            int n = n0 + nof + j * 8 + 2 * q;
            by[j][0] = b_ya[n];
            by[j][1] = b_ya[n + 1];
        }
    }

    auto loadA = [&](int buf, int ck, const __half* a_src) {
#pragma unroll
        for (int r = 0; r < 2; ++r) {
            int u = tid + r * 256;       // 0..511
            int row = u >> 3, cg = u & 7;
            cp_async16(Asm + buf * (64 * 72) + row * 72 + cg * 8,
                       a_src + (size_t)row * HH + ck * 64 + cg * 8);
        }
    };

    for (int it = 0; it < TT + 1; ++it) {
        const __half* a_cur = g_a[it & 1];
        const bool active = is_aa ? (it < TT) : (it >= 1);

        if (active) {
            float acc[2][4];
#pragma unroll
            for (int j = 0; j < 2; ++j)
#pragma unroll
                for (int c = 0; c < 4; ++c) acc[j][c] = 0.0f;

            loadA(0, 0, a_cur);
            cp_commit();
            const int NCH = HH / 64;   // 32
            for (int ck = 0; ck < NCH; ++ck) {
                if (ck + 1 < NCH) { loadA((ck + 1) & 1, ck + 1, a_cur); cp_commit(); cp_wait1(); }
                else cp_wait0();
                __syncthreads();
                const __half* Ab = Asm + (ck & 1) * (64 * 72);
#pragma unroll
                for (int s = 0; s < 4; ++s) {
                    uint32_t a0, a1, a2, a3, b0, b1, b2, b3;
                    ldsm4(a0, a1, a2, a3, Ab + (wm + arow) * 72 + s * 16 + akoff);
                    ldsm4(b0, b1, b2, b3, Wsm + (nof + brow) * WPAD + ck * 64 + s * 16 + bkoff);
                    mma16816(acc[0], a0, a1, a2, a3, b0, b1);
                    mma16816(acc[1], a0, a1, a2, a3, b2, b3);
                }
                __syncthreads();
            }

            if (is_aa) {
                // a_{it+1} = sigmoid(acc + Z[it])
                __half* adst = g_a[(it + 1) & 1];
                const float* Zb = g_Z + (size_t)it * 64 * HH;
#pragma unroll
                for (int j = 0; j < 2; ++j) {
                    int n = n0 + nof + j * 8 + 2 * q;
                    size_t i0 = (size_t)(wm + gr) * HH + n;
                    float2 z0 = *(const float2*)(Zb + i0);
                    *(__half2*)(adst + i0) =
                        __floats2half2_rn(sigf(acc[j][0] + z0.x), sigf(acc[j][1] + z0.y));
                    size_t i1 = i0 + (size_t)8 * HH;
                    float2 z1 = *(const float2*)(Zb + i1);
                    *(__half2*)(adst + i1) =
                        __floats2half2_rn(sigf(acc[j][2] + z1.x), sigf(acc[j][3] + z1.y));
                }
            } else {
                // y_{it-1} = sigmoid(acc + b_ya); out row = (t*64 + b)
                float* ob = out + (size_t)(it - 1) * 64 * OO;
#pragma unroll
                for (int j = 0; j < 2; ++j) {
                    int n = n0 + nof + j * 8 + 2 * q;
                    size_t i0 = (size_t)(wm + gr) * OO + n;
                    *(float2*)(ob + i0) =
                        make_float2(sigf(acc[j][0] + by[j][0]), sigf(acc[j][1] + by[j][1]));
                    size_t i1 = i0 + (size_t)8 * OO;
                    *(float2*)(ob + i1) =
                        make_float2(sigf(acc[j][2] + by[j][0]), sigf(acc[j][3] + by[j][1]));
                }
            }
        }

        // -------- grid barrier --------
        __threadfence();
        __syncthreads();
        if (tid == 0) {
            atomicAdd(&g_bar, 1u);
            unsigned target = (unsigned)(it + 1) * NCTA;
            while (*(volatile unsigned*)&g_bar < target) { }
        }
        __syncthreads();
    }
}

// ---------------- launch ----------------
extern "C" void kernel_launch(void* const* d_in, const int* in_sizes, int n_in,
                              void* d_out, int out_size) {
    const float* x    = (const float*)d_in[0];
    const float* Waa  = (const float*)d_in[1];
    const float* b_aa = (const float*)d_in[2];
    const float* Wax  = (const float*)d_in[3];
    const float* b_ax = (const float*)d_in[4];
    const float* Wya  = (const float*)d_in[5];
    const float* b_ya = (const float*)d_in[6];
    float* out = (float*)d_out;

    static bool attr_done = false;
    if (!attr_done) {
        cudaFuncSetAttribute(xproj_kernel, cudaFuncAttributeMaxDynamicSharedMemorySize, XP_SMEM);
        cudaFuncSetAttribute(rnn_persistent, cudaFuncAttributeMaxDynamicSharedMemorySize, PERS_SMEM);
        attr_done = true;
    }

    int prep_blocks = (int)((NPREP + 255) / 256);
    prep_kernel<<<prep_blocks, 256>>>(x, Waa, Wax, Wya);

    dim3 xg(HH / 128, (TT * BB) / 128);   // 16 x 128
    xproj_kernel<<<xg, 256, XP_SMEM>>>(b_aa, b_ax);

    rnn_persistent<<<NCTA, 256, PERS_SMEM>>>(out, b_ya);
}

// round 4
// speedup vs baseline: 1.1646x; 1.1646x over previous
#include <cuda_runtime.h>
#include <cuda_fp16.h>
#include <cstdint>

#define BB 64
#define TT 256
#define II 1024
#define HH 2048
#define OO 1024

// ---------------- device scratch ----------------
__device__ __half g_xh[(size_t)BB * TT * II];
__device__ __half g_Wax[(size_t)HH * II];
__device__ __half g_Waa[(size_t)HH * HH];
__device__ __half g_Wya[(size_t)OO * HH];
__device__ float  g_Z[(size_t)TT * BB * HH];      // x W_ax^T + b_ax + b_aa (fp32)
__device__ __half g_a[2][(size_t)BB * HH];        // double-buffered hidden state
__device__ unsigned g_bar;

// ---------------- helpers ----------------
__device__ __forceinline__ uint32_t sptr(const void* p) {
    return (uint32_t)__cvta_generic_to_shared(p);
}
__device__ __forceinline__ void cp_async16(const void* dst_smem, const void* src) {
    asm volatile("cp.async.cg.shared.global [%0], [%1], 16;"
                 :: "r"(sptr(dst_smem)), "l"(src));
}
__device__ __forceinline__ void cp_commit() { asm volatile("cp.async.commit_group;"); }
__device__ __forceinline__ void cp_wait0()  { asm volatile("cp.async.wait_group 0;"); }
__device__ __forceinline__ void cp_wait1()  { asm volatile("cp.async.wait_group 1;"); }

__device__ __forceinline__ void ldsm4(uint32_t& r0, uint32_t& r1, uint32_t& r2, uint32_t& r3,
                                      const void* p) {
    asm volatile("ldmatrix.sync.aligned.m8n8.x4.shared.b16 {%0,%1,%2,%3},[%4];"
                 : "=r"(r0), "=r"(r1), "=r"(r2), "=r"(r3) : "r"(sptr(p)));
}
__device__ __forceinline__ void mma16816(float* c,
                                         uint32_t a0, uint32_t a1, uint32_t a2, uint32_t a3,
                                         uint32_t b0, uint32_t b1) {
    asm volatile("mma.sync.aligned.m16n8k16.row.col.f32.f16.f16.f32 "
                 "{%0,%1,%2,%3},{%4,%5,%6,%7},{%8,%9},{%0,%1,%2,%3};"
                 : "+f"(c[0]), "+f"(c[1]), "+f"(c[2]), "+f"(c[3])
                 : "r"(a0), "r"(a1), "r"(a2), "r"(a3), "r"(b0), "r"(b1));
}
__device__ __forceinline__ float sigf(float v) { return 1.0f / (1.0f + __expf(-v)); }

// ---------------- prep (vectorized x4) ----------------
#define NX  ((size_t)BB * TT * II)
#define NAA ((size_t)HH * HH)
#define NAX ((size_t)HH * II)
#define NYA ((size_t)OO * HH)
#define NA0 ((size_t)BB * HH)
#define NPREP4 ((NX + NAA + NAX + NYA + NA0) / 4)

__device__ __forceinline__ void cvt4(__half* dst, const float* src, size_t i4) {
    float4 v = *(const float4*)(src + i4 * 4);
    __half2 h0 = __floats2half2_rn(v.x, v.y);
    __half2 h1 = __floats2half2_rn(v.z, v.w);
    *(uint2*)(dst + i4 * 4) = make_uint2(*(uint32_t*)&h0, *(uint32_t*)&h1);
}

__global__ void prep_kernel(const float* __restrict__ x, const float* __restrict__ Waa,
                            const float* __restrict__ Wax, const float* __restrict__ Wya) {
    size_t i = (size_t)blockIdx.x * blockDim.x + threadIdx.x;
    if (i == 0) g_bar = 0u;
    if (i < NX / 4) { cvt4(g_xh, x, i); return; }
    i -= NX / 4;
    if (i < NAA / 4) { cvt4(g_Waa, Waa, i); return; }
    i -= NAA / 4;
    if (i < NAX / 4) { cvt4(g_Wax, Wax, i); return; }
    i -= NAX / 4;
    if (i < NYA / 4) { cvt4(g_Wya, Wya, i); return; }
    i -= NYA / 4;
    if (i < NA0 / 4) { *(uint2*)(g_a[0] + i * 4) = make_uint2(0u, 0u); }
}

// ---------------- xproj: Z = x W_ax^T + biases ----------------
#define XP_SMEM (2 * (2 * 128 * 72 * 2))

__global__ void __launch_bounds__(256) xproj_kernel(const float* __restrict__ b_aa,
                                                    const float* __restrict__ b_ax) {
    extern __shared__ __align__(16) unsigned char smraw[];
    __half* As = (__half*)smraw;                       // [2][128][72]
    __half* Bs = (__half*)(smraw + 2 * 128 * 72 * 2);  // [2][128][72]

    const int tid = threadIdx.x;
    const int lane = tid & 31, warp = tid >> 5;
    const int n0 = blockIdx.x * 128;
    const int m0 = blockIdx.y * 128;
    const int wm = (warp >> 1) * 32;
    const int wn = (warp & 1) * 64;
    const int gr = lane >> 2, q = lane & 3;

    const int arow = ((lane >> 3) & 1) * 8 + (lane & 7);
    const int akoff = (lane >> 4) * 8;
    const int brow = (lane >> 4) * 8 + (lane & 7);
    const int bkoff = ((lane >> 3) & 1) * 8;

    float acc[2][8][4];
#pragma unroll
    for (int f = 0; f < 2; ++f)
#pragma unroll
        for (int bt = 0; bt < 8; ++bt)
#pragma unroll
            for (int c = 0; c < 4; ++c) acc[f][bt][c] = 0.0f;

    auto load_chunk = [&](int buf, int ck) {
#pragma unroll
        for (int r = 0; r < 4; ++r) {
            int u = tid + r * 256;
            int row = u >> 3, cg = u & 7;
            int m = m0 + row;
            int t = m >> 6, b = m & 63;
            cp_async16(As + buf * (128 * 72) + row * 72 + cg * 8,
                       g_xh + ((size_t)b * TT + t) * II + ck * 64 + cg * 8);
            cp_async16(Bs + buf * (128 * 72) + row * 72 + cg * 8,
                       g_Wax + (size_t)(n0 + row) * II + ck * 64 + cg * 8);
        }
    };

    load_chunk(0, 0);
    cp_commit();
    const int NCH = II / 64;  // 16
    for (int ck = 0; ck < NCH; ++ck) {
        if (ck + 1 < NCH) { load_chunk((ck + 1) & 1, ck + 1); cp_commit(); cp_wait1(); }
        else cp_wait0();
        __syncthreads();
        const __half* Ab = As + (ck & 1) * (128 * 72);
        const __half* Bb = Bs + (ck & 1) * (128 * 72);
#pragma unroll
        for (int s = 0; s < 4; ++s) {
            uint32_t a[2][4];
#pragma unroll
            for (int f = 0; f < 2; ++f)
                ldsm4(a[f][0], a[f][1], a[f][2], a[f][3],
                      Ab + (wm + f * 16 + arow) * 72 + s * 16 + akoff);
#pragma unroll
            for (int bp = 0; bp < 4; ++bp) {
                uint32_t b0, b1, b2, b3;
                ldsm4(b0, b1, b2, b3,
                      Bb + (wn + bp * 16 + brow) * 72 + s * 16 + bkoff);
#pragma unroll
                for (int f = 0; f < 2; ++f) {
                    mma16816(acc[f][2 * bp],     a[f][0], a[f][1], a[f][2], a[f][3], b0, b1);
                    mma16816(acc[f][2 * bp + 1], a[f][0], a[f][1], a[f][2], a[f][3], b2, b3);
                }
            }
        }
        __syncthreads();
    }

    float bs0[8], bs1[8];
#pragma unroll
    for (int bt = 0; bt < 8; ++bt) {
        int n = n0 + wn + bt * 8 + 2 * q;
        bs0[bt] = b_ax[n] + b_aa[n];
        bs1[bt] = b_ax[n + 1] + b_aa[n + 1];
    }
#pragma unroll
    for (int f = 0; f < 2; ++f) {
#pragma unroll
        for (int bt = 0; bt < 8; ++bt) {
            int mlo = wm + f * 16 + gr;
            int n = wn + bt * 8 + 2 * q;
            size_t zi = (size_t)(m0 + mlo) * HH + n0 + n;
            *(float2*)(g_Z + zi) =
                make_float2(acc[f][bt][0] + bs0[bt], acc[f][bt][1] + bs1[bt]);
            *(float2*)(g_Z + zi + (size_t)8 * HH) =
                make_float2(acc[f][bt][2] + bs0[bt], acc[f][bt][3] + bs1[bt]);
        }
    }
}

// ---------------- persistent recurrence ----------------
// 96 CTAs: 0..63 own 32-col slices of W_aa, 64..95 own 32-col slices of W_ya.
// Weights persist in SMEM. Chunk=128 cols, 3-buffer ring, depth-2 prefetch,
// ONE __syncthreads per chunk. One grid barrier per step.
#define NCTA 96
#define WPAD 2056
#define CHUNK 128
#define NCH (HH / CHUNK)          // 16
#define ASTRIDE 136               // 128 + 8 pad -> conflict-free ldmatrix
#define ABUF (64 * ASTRIDE)       // halves per buffer
#define PERS_SMEM (32 * WPAD * 2 + 3 * ABUF * 2)   // 131584 + 52224 = 183808 B

__global__ void __launch_bounds__(256) rnn_persistent(float* __restrict__ out,
                                                      const float* __restrict__ b_ya) {
    extern __shared__ __align__(16) unsigned char smraw[];
    __half* Wsm = (__half*)smraw;                       // [32][WPAD]
    __half* Asm = (__half*)(smraw + 32 * WPAD * 2);     // [3][64][ASTRIDE]

    const int tid = threadIdx.x;
    const int lane = tid & 31, warp = tid >> 5;
    const int cta = blockIdx.x;
    const bool is_aa = (cta < 64);
    const int n0 = is_aa ? cta * 32 : (cta - 64) * 32;
    const __half* Wg = is_aa ? g_Waa : g_Wya;

    // preload persistent 32 x 2048 weight slice
    for (int u = tid; u < 32 * 256; u += 256) {
        int row = u >> 8, cg = u & 255;
        cp_async16(Wsm + row * WPAD + cg * 8, Wg + (size_t)(n0 + row) * HH + cg * 8);
    }
    cp_commit();
    cp_wait0();
    __syncthreads();

    const int wm = (warp >> 1) * 16;   // 4 m-groups of 16 batch rows
    const int nof = (warp & 1) * 16;   // 2 n-groups of 16 cols
    const int gr = lane >> 2, q = lane & 3;
    const int arow = ((lane >> 3) & 1) * 8 + (lane & 7);
    const int akoff = (lane >> 4) * 8;
    const int brow = (lane >> 4) * 8 + (lane & 7);
    const int bkoff = ((lane >> 3) & 1) * 8;

    float by[2][2];
    if (!is_aa) {
#pragma unroll
        for (int j = 0; j < 2; ++j) {
            int n = n0 + nof + j * 8 + 2 * q;
            by[j][0] = b_ya[n];
            by[j][1] = b_ya[n + 1];
        }
    }

    // chunk = 64 rows x 128 halves = 1024 x 16B segments, 4 per thread
    auto loadA = [&](int buf, int ck, const __half* a_src) {
#pragma unroll
        for (int r = 0; r < 4; ++r) {
            int u = tid + r * 256;
            int row = u >> 4, seg = u & 15;
            cp_async16(Asm + buf * ABUF + row * ASTRIDE + seg * 8,
                       a_src + (size_t)row * HH + ck * CHUNK + seg * 8);
        }
    };

    for (int it = 0; it < TT + 1; ++it) {
        const __half* a_cur = g_a[it & 1];
        const bool active = is_aa ? (it < TT) : (it >= 1);

        if (active) {
            float acc[2][4];
#pragma unroll
            for (int j = 0; j < 2; ++j)
#pragma unroll
                for (int c = 0; c < 4; ++c) acc[j][c] = 0.0f;

            loadA(0, 0, a_cur); cp_commit();
            loadA(1, 1, a_cur); cp_commit();

            for (int ck = 0; ck < NCH; ++ck) {
                if (ck < NCH - 1) cp_wait1(); else cp_wait0();
                __syncthreads();      // chunk ck visible; all warps done with ck-1
                if (ck + 2 < NCH) { loadA((ck + 2) % 3, ck + 2, a_cur); cp_commit(); }
                const __half* Ab = Asm + (ck % 3) * ABUF;
#pragma unroll
                for (int s = 0; s < CHUNK / 16; ++s) {
                    uint32_t a0, a1, a2, a3, b0, b1, b2, b3;
                    ldsm4(a0, a1, a2, a3, Ab + (wm + arow) * ASTRIDE + s * 16 + akoff);
                    ldsm4(b0, b1, b2, b3,
                          Wsm + (nof + brow) * WPAD + ck * CHUNK + s * 16 + bkoff);
                    mma16816(acc[0], a0, a1, a2, a3, b0, b1);
                    mma16816(acc[1], a0, a1, a2, a3, b2, b3);
                }
            }

            if (is_aa) {
                __half* adst = g_a[(it + 1) & 1];
                const float* Zb = g_Z + (size_t)it * 64 * HH;
#pragma unroll
                for (int j = 0; j < 2; ++j) {
                    int n = n0 + nof + j * 8 + 2 * q;
                    size_t i0 = (size_t)(wm + gr) * HH + n;
                    float2 z0 = *(const float2*)(Zb + i0);
                    *(__half2*)(adst + i0) =
                        __floats2half2_rn(sigf(acc[j][0] + z0.x), sigf(acc[j][1] + z0.y));
                    size_t i1 = i0 + (size_t)8 * HH;
                    float2 z1 = *(const float2*)(Zb + i1);
                    *(__half2*)(adst + i1) =
                        __floats2half2_rn(sigf(acc[j][2] + z1.x), sigf(acc[j][3] + z1.y));
                }
            } else {
                float* ob = out + (size_t)(it - 1) * 64 * OO;
#pragma unroll
                for (int j = 0; j < 2; ++j) {
                    int n = n0 + nof + j * 8 + 2 * q;
                    size_t i0 = (size_t)(wm + gr) * OO + n;
                    *(float2*)(ob + i0) =
                        make_float2(sigf(acc[j][0] + by[j][0]), sigf(acc[j][1] + by[j][1]));
                    size_t i1 = i0 + (size_t)8 * OO;
                    *(float2*)(ob + i1) =
                        make_float2(sigf(acc[j][2] + by[j][0]), sigf(acc[j][3] + by[j][1]));
                }
            }
        }

        // -------- grid barrier --------
        __threadfence();
        __syncthreads();
        if (tid == 0) {
            atomicAdd(&g_bar, 1u);
            unsigned target = (unsigned)(it + 1) * NCTA;
            while (*(volatile unsigned*)&g_bar < target) { }
        }
        __syncthreads();
    }
}

// ---------------- launch ----------------
extern "C" void kernel_launch(void* const* d_in, const int* in_sizes, int n_in,
                              void* d_out, int out_size) {
    const float* x    = (const float*)d_in[0];
    const float* Waa  = (const float*)d_in[1];
    const float* b_aa = (const float*)d_in[2];
    const float* Wax  = (const float*)d_in[3];
    const float* b_ax = (const float*)d_in[4];
    const float* Wya  = (const float*)d_in[5];
    const float* b_ya = (const float*)d_in[6];
    float* out = (float*)d_out;

    static bool attr_done = false;
    if (!attr_done) {
        cudaFuncSetAttribute(xproj_kernel, cudaFuncAttributeMaxDynamicSharedMemorySize, XP_SMEM);
        cudaFuncSetAttribute(rnn_persistent, cudaFuncAttributeMaxDynamicSharedMemorySize, PERS_SMEM);
        attr_done = true;
    }

    int prep_blocks = (int)((NPREP4 + 255) / 256);
    prep_kernel<<<prep_blocks, 256>>>(x, Waa, Wax, Wya);

    dim3 xg(HH / 128, (TT * BB) / 128);
    xproj_kernel<<<xg, 256, XP_SMEM>>>(b_aa, b_ax);

    rnn_persistent<<<NCTA, 256, PERS_SMEM>>>(out, b_ya);
}